// round 1
// baseline (speedup 1.0000x reference)
#include <cuda_runtime.h>

#define NN 50000
#define EE 400000
#define GG 2048
#define HH 4
#define CC 64
#define HC 256
#define IND 29
#define EDD 6
#define NTASK 12
#define ET (EE + NN)

// ---------------- scratch (static device globals; no allocation) ----------------
__device__ float    g_h[NN * HC];        // h = feat @ W   [N,256]
__device__ float    g_acc[NN * HC];      // message accumulator
__device__ float    g_feat[NN * HC];     // layer output / next layer input
__device__ float    g_alpha[ET * HH];    // per-edge per-head attention scratch
__device__ float    g_als[NN * HH];
__device__ float    g_ald[NN * HH];
__device__ unsigned g_amax[NN * HH];     // ordered-uint encoded max
__device__ float    g_den[NN * HH];
__device__ float    g_ve[EDD * HH];      // collapsed We*ae  [6,4]
__device__ float    g_selfale[HH];
__device__ float    g_mesum[EDD];
__device__ float    g_pool[GG * HC];
__device__ float    g_cnt[GG];

// ordered-uint mapping for float atomicMax
__device__ __forceinline__ unsigned fenc(float f) {
    unsigned u = __float_as_uint(f);
    return (u & 0x80000000u) ? ~u : (u | 0x80000000u);
}
__device__ __forceinline__ float fdec(unsigned e) {
    return (e & 0x80000000u) ? __uint_as_float(e & 0x7fffffffu)
                             : __uint_as_float(~e);
}

// ---------------- utility ----------------
__global__ void k_zero(float* p, int n) {
    int i = blockIdx.x * blockDim.x + threadIdx.x;
    int stride = gridDim.x * blockDim.x;
    for (; i < n; i += stride) p[i] = 0.0f;
}

// column sums of edge_attr [E,6]
__global__ void k_meansum(const float* __restrict__ ea) {
    float loc[EDD];
#pragma unroll
    for (int j = 0; j < EDD; j++) loc[j] = 0.0f;
    int i = blockIdx.x * blockDim.x + threadIdx.x;
    int stride = gridDim.x * blockDim.x;
    for (int e = i; e < EE; e += stride) {
#pragma unroll
        for (int j = 0; j < EDD; j++) loc[j] += ea[e * EDD + j];
    }
#pragma unroll
    for (int j = 0; j < EDD; j++) {
        float v = loc[j];
#pragma unroll
        for (int off = 16; off > 0; off >>= 1)
            v += __shfl_down_sync(0xffffffffu, v, off);
        if ((threadIdx.x & 31) == 0) atomicAdd(&g_mesum[j], v);
    }
}

// collapse We (ED,HC) with ae (H,C) -> ve[6,4]; self-loop al_e per head
__global__ void k_ve(const float* __restrict__ We, const float* __restrict__ ae) {
    int t = threadIdx.x;
    if (t < EDD * HH) {
        int j = t / HH, h = t % HH;
        float s = 0.0f;
#pragma unroll
        for (int c = 0; c < CC; c++) s += We[j * HC + h * CC + c] * ae[h * CC + c];
        g_ve[j * HH + h] = s;
    }
    __syncthreads();
    if (t < HH) {
        float s = 0.0f;
#pragma unroll
        for (int j = 0; j < EDD; j++)
            s += (g_mesum[j] / (float)EE) * g_ve[j * HH + t];
        g_selfale[t] = s;
    }
}

// layer-1 GEMM: h = x(N,29) @ W(29,256). 32 rows per block, W column in regs.
__global__ __launch_bounds__(256) void k_gemm_l1(const float* __restrict__ x,
                                                 const float* __restrict__ W) {
    __shared__ float fs[32][IND];
    int n0 = blockIdx.x * 32;
    int tid = threadIdx.x;
    for (int i = tid; i < 32 * IND; i += 256) {
        int r = i / IND, k = i % IND;
        int n = n0 + r;
        fs[r][k] = (n < NN) ? x[n * IND + k] : 0.0f;
    }
    float wr[IND];
#pragma unroll
    for (int k = 0; k < IND; k++) wr[k] = __ldg(&W[k * HC + tid]);
    __syncthreads();
#pragma unroll 4
    for (int r = 0; r < 32; r++) {
        int n = n0 + r;
        if (n >= NN) break;
        float s = 0.0f;
#pragma unroll
        for (int k = 0; k < IND; k++) s += fs[r][k] * wr[k];
        g_h[n * HC + tid] = s;
    }
}

// layer-2 GEMM: C(N,256) = A(N,256) @ B(256,256). 64x64 tile, 4x4/thread.
#define BM 64
#define BN 64
#define BK 16
__global__ __launch_bounds__(256) void k_gemm256(const float* __restrict__ A,
                                                 const float* __restrict__ B) {
    __shared__ float As[BK][BM + 4];
    __shared__ float Bs[BK][BN];
    int row0 = blockIdx.y * BM;
    int col0 = blockIdx.x * BN;
    int tid = threadIdx.x;
    int tr = tid / 16, tc = tid % 16;
    int a_row = tid / 4;
    int a_k4 = (tid % 4) * 4;
    int b_k = tid / 16;
    int b_c4 = (tid % 16) * 4;
    float acc[4][4];
#pragma unroll
    for (int i = 0; i < 4; i++)
#pragma unroll
        for (int j = 0; j < 4; j++) acc[i][j] = 0.0f;

    for (int k0 = 0; k0 < HC; k0 += BK) {
        float4 av = make_float4(0.f, 0.f, 0.f, 0.f);
        if (row0 + a_row < NN)
            av = *(const float4*)&A[(row0 + a_row) * HC + k0 + a_k4];
        As[a_k4 + 0][a_row] = av.x;
        As[a_k4 + 1][a_row] = av.y;
        As[a_k4 + 2][a_row] = av.z;
        As[a_k4 + 3][a_row] = av.w;
        float4 bv = *(const float4*)&B[(k0 + b_k) * HC + col0 + b_c4];
        *(float4*)&Bs[b_k][b_c4] = bv;
        __syncthreads();
#pragma unroll
        for (int k = 0; k < BK; k++) {
            float4 a4 = *(const float4*)&As[k][tr * 4];
            float4 b4 = *(const float4*)&Bs[k][tc * 4];
            float ar[4] = {a4.x, a4.y, a4.z, a4.w};
            float br[4] = {b4.x, b4.y, b4.z, b4.w};
#pragma unroll
            for (int i = 0; i < 4; i++)
#pragma unroll
                for (int j = 0; j < 4; j++) acc[i][j] += ar[i] * br[j];
        }
        __syncthreads();
    }
#pragma unroll
    for (int i = 0; i < 4; i++) {
        int row = row0 + tr * 4 + i;
        if (row < NN) {
            float4 v = make_float4(acc[i][0], acc[i][1], acc[i][2], acc[i][3]);
            *(float4*)&g_h[row * HC + col0 + tc * 4] = v;
        }
    }
}

// al_s / al_d: warp per node, dot h[n,h,:] with a_src / a_dst
__global__ __launch_bounds__(256) void k_att(const float* __restrict__ a_s,
                                             const float* __restrict__ a_d) {
    int w = (blockIdx.x * blockDim.x + threadIdx.x) >> 5;
    int lane = threadIdx.x & 31;
    if (w >= NN) return;
    const float* hr = &g_h[w * HC];
    float ps[4] = {0, 0, 0, 0}, pd[4] = {0, 0, 0, 0};
#pragma unroll
    for (int it = 0; it < 8; it++) {
        int j = lane + 32 * it;
        float hv = hr[j];
        ps[it >> 1] += hv * __ldg(&a_s[j]);
        pd[it >> 1] += hv * __ldg(&a_d[j]);
    }
#pragma unroll
    for (int h = 0; h < HH; h++) {
        float v = ps[h], u = pd[h];
#pragma unroll
        for (int off = 16; off > 0; off >>= 1) {
            v += __shfl_down_sync(0xffffffffu, v, off);
            u += __shfl_down_sync(0xffffffffu, u, off);
        }
        if (lane == 0) {
            g_als[w * HH + h] = v;
            g_ald[w * HH + h] = u;
        }
    }
}

// alpha = leaky(al_s[src] + al_d[dst] + al_e); atomicMax segment max on dst
__global__ __launch_bounds__(256) void k_alpha(const int* __restrict__ ei,
                                               const float* __restrict__ ea) {
    int e = blockIdx.x * blockDim.x + threadIdx.x;
    if (e >= ET) return;
    int src, dst;
    float ale[HH];
    if (e < EE) {
        src = ei[e];
        dst = ei[EE + e];
        float er[EDD];
#pragma unroll
        for (int j = 0; j < EDD; j++) er[j] = ea[e * EDD + j];
#pragma unroll
        for (int h = 0; h < HH; h++) {
            float s = 0.0f;
#pragma unroll
            for (int j = 0; j < EDD; j++) s += er[j] * __ldg(&g_ve[j * HH + h]);
            ale[h] = s;
        }
    } else {
        src = dst = e - EE;
#pragma unroll
        for (int h = 0; h < HH; h++) ale[h] = __ldg(&g_selfale[h]);
    }
    float4 s4 = *(const float4*)&g_als[src * HH];
    float4 d4 = *(const float4*)&g_ald[dst * HH];
    float a[4] = {s4.x + d4.x + ale[0], s4.y + d4.y + ale[1],
                  s4.z + d4.z + ale[2], s4.w + d4.w + ale[3]};
#pragma unroll
    for (int h = 0; h < HH; h++) {
        float v = a[h];
        v = (v > 0.0f) ? v : 0.2f * v;
        a[h] = v;
        atomicMax(&g_amax[dst * HH + h], fenc(v));
    }
    *(float4*)&g_alpha[e * HH] = make_float4(a[0], a[1], a[2], a[3]);
}

// ex = exp(alpha - max); segment sum on dst
__global__ __launch_bounds__(256) void k_exp(const int* __restrict__ ei) {
    int e = blockIdx.x * blockDim.x + threadIdx.x;
    if (e >= ET) return;
    int dst = (e < EE) ? ei[EE + e] : (e - EE);
    float4 al = *(const float4*)&g_alpha[e * HH];
    float a[4] = {al.x, al.y, al.z, al.w};
#pragma unroll
    for (int h = 0; h < HH; h++) {
        float m = fdec(g_amax[dst * HH + h]);
        float ex = __expf(a[h] - m);
        a[h] = ex;
        atomicAdd(&g_den[dst * HH + h], ex);
    }
    *(float4*)&g_alpha[e * HH] = make_float4(a[0], a[1], a[2], a[3]);
}

// message: acc[dst] += h[src] * (ex / den[dst]). warp per edge.
__global__ __launch_bounds__(256) void k_msg(const int* __restrict__ ei) {
    int w = (blockIdx.x * blockDim.x + threadIdx.x) >> 5;
    if (w >= ET) return;
    int lane = threadIdx.x & 31;
    int src, dst;
    if (w < EE) {
        src = ei[w];
        dst = ei[EE + w];
    } else {
        src = dst = w - EE;
    }
    float4 exv = *(const float4*)&g_alpha[w * HH];
    float4 dn = *(const float4*)&g_den[dst * HH];
    float wg[4] = {exv.x / (dn.x + 1e-16f), exv.y / (dn.y + 1e-16f),
                   exv.z / (dn.z + 1e-16f), exv.w / (dn.w + 1e-16f)};
    const float* hs = &g_h[src * HC];
    float* ac = &g_acc[dst * HC];
#pragma unroll
    for (int it = 0; it < 8; it++) {
        int j = lane + 32 * it;
        atomicAdd(&ac[j], hs[j] * wg[it >> 1]);
    }
}

// feat = relu(acc + b)
__global__ void k_bias_relu(const float* __restrict__ b) {
    int i = blockIdx.x * blockDim.x + threadIdx.x;
    if (i >= NN * HC / 4) return;
    float4 v = ((const float4*)g_acc)[i];
    float4 bb = __ldg(&((const float4*)b)[i & 63]);
    v.x = fmaxf(v.x + bb.x, 0.0f);
    v.y = fmaxf(v.y + bb.y, 0.0f);
    v.z = fmaxf(v.z + bb.z, 0.0f);
    v.w = fmaxf(v.w + bb.w, 0.0f);
    ((float4*)g_feat)[i] = v;
}

// mean-pool accumulation: warp per node
__global__ __launch_bounds__(256) void k_pool(const int* __restrict__ batch) {
    int w = (blockIdx.x * blockDim.x + threadIdx.x) >> 5;
    if (w >= NN) return;
    int lane = threadIdx.x & 31;
    int g = batch[w];
    const float* fr = &g_feat[w * HC];
    float* pr = &g_pool[g * HC];
#pragma unroll
    for (int it = 0; it < 8; it++) {
        int j = lane + 32 * it;
        atomicAdd(&pr[j], fr[j]);
    }
    if (lane == 0) atomicAdd(&g_cnt[g], 1.0f);
}

// out[g,t] = (pool[g,:]/cnt) @ Wl[:,t] + bl[t]
__global__ void k_out(const float* __restrict__ Wl, const float* __restrict__ bl,
                      float* __restrict__ out) {
    int i = blockIdx.x * blockDim.x + threadIdx.x;
    if (i >= GG * NTASK) return;
    int g = i / NTASK, t = i % NTASK;
    float inv = 1.0f / fmaxf(g_cnt[g], 1.0f);
    float s = 0.0f;
    const float* pr = &g_pool[g * HC];
#pragma unroll 8
    for (int j = 0; j < HC; j++) s += pr[j] * __ldg(&Wl[j * NTASK + t]);
    out[i] = s * inv + bl[t];
}

// ---------------- host orchestration ----------------
static inline int cdiv(int a, int b) { return (a + b - 1) / b; }

extern "C" void kernel_launch(void* const* d_in, const int* in_sizes, int n_in,
                              void* d_out, int out_size) {
    const float* x   = (const float*)d_in[0];
    const int*   ei  = (const int*)d_in[1];
    const float* ea  = (const float*)d_in[2];
    const int*   bat = (const int*)d_in[3];
    const float* W1  = (const float*)d_in[4];
    const float* as1 = (const float*)d_in[5];
    const float* ad1 = (const float*)d_in[6];
    const float* We1 = (const float*)d_in[7];
    const float* ae1 = (const float*)d_in[8];
    const float* b1  = (const float*)d_in[9];
    const float* W2  = (const float*)d_in[10];
    const float* as2 = (const float*)d_in[11];
    const float* ad2 = (const float*)d_in[12];
    const float* We2 = (const float*)d_in[13];
    const float* ae2 = (const float*)d_in[14];
    const float* b2  = (const float*)d_in[15];
    const float* Wl  = (const float*)d_in[16];
    const float* bl  = (const float*)d_in[17];
    float* out = (float*)d_out;

    float* p_mesum; cudaGetSymbolAddress((void**)&p_mesum, g_mesum);
    float* p_den;   cudaGetSymbolAddress((void**)&p_den, g_den);
    float* p_amax;  cudaGetSymbolAddress((void**)&p_amax, g_amax);
    float* p_acc;   cudaGetSymbolAddress((void**)&p_acc, g_acc);
    float* p_pool;  cudaGetSymbolAddress((void**)&p_pool, g_pool);
    float* p_cnt;   cudaGetSymbolAddress((void**)&p_cnt, g_cnt);

    // edge_attr mean (shared across both layers)
    k_zero<<<1, 256>>>(p_mesum, EDD);
    k_meansum<<<512, 256>>>(ea);

    // ---- layer 1 ----
    k_ve<<<1, 256>>>(We1, ae1);
    k_gemm_l1<<<cdiv(NN, 32), 256>>>(x, W1);
    k_att<<<cdiv(NN * 32, 256), 256>>>(as1, ad1);
    k_zero<<<256, 256>>>(p_den, NN * HH);
    k_zero<<<256, 256>>>(p_amax, NN * HH);
    k_zero<<<2048, 256>>>(p_acc, NN * HC);
    k_alpha<<<cdiv(ET, 256), 256>>>(ei, ea);
    k_exp<<<cdiv(ET, 256), 256>>>(ei);
    k_msg<<<cdiv(ET * 32, 256), 256>>>(ei);
    k_bias_relu<<<cdiv(NN * HC / 4, 256), 256>>>(b1);

    // ---- layer 2 ----
    k_ve<<<1, 256>>>(We2, ae2);
    {
        float* p_feat; cudaGetSymbolAddress((void**)&p_feat, g_feat);
        dim3 grid(HC / BN, cdiv(NN, BM));
        k_gemm256<<<grid, 256>>>(p_feat, W2);
    }
    k_att<<<cdiv(NN * 32, 256), 256>>>(as2, ad2);
    k_zero<<<256, 256>>>(p_den, NN * HH);
    k_zero<<<256, 256>>>(p_amax, NN * HH);
    k_zero<<<2048, 256>>>(p_acc, NN * HC);
    k_alpha<<<cdiv(ET, 256), 256>>>(ei, ea);
    k_exp<<<cdiv(ET, 256), 256>>>(ei);
    k_msg<<<cdiv(ET * 32, 256), 256>>>(ei);
    k_bias_relu<<<cdiv(NN * HC / 4, 256), 256>>>(b2);

    // ---- readout ----
    k_zero<<<512, 256>>>(p_pool, GG * HC);
    k_zero<<<8, 256>>>(p_cnt, GG);
    k_pool<<<cdiv(NN * 32, 256), 256>>>(bat);
    k_out<<<cdiv(GG * NTASK, 256), 256>>>(Wl, bl, out);
}

// round 2
// speedup vs baseline: 1.5254x; 1.5254x over previous
#include <cuda_runtime.h>

#define NN 50000
#define EE 400000
#define GG 2048
#define HH 4
#define CC 64
#define HC 256
#define IND 29
#define EDD 6
#define NTASK 12
#define ET (EE + NN)

// ---------------- scratch (static device globals) ----------------
__device__ float g_h[NN * HC];        // h = feat @ W
__device__ float g_feat[NN * HC];     // layer output
__device__ float g_als[NN * HH];
__device__ float g_ald[NN * HH];
__device__ float g_ve[EDD * HH];      // collapsed We*ae [6,4]
__device__ float g_mesum[EDD];
__device__ int   g_deg[NN];
__device__ int   g_start[NN + 1];
__device__ int   g_cursor[NN];
__device__ int   g_csr_src[ET];
__device__ float g_csr_ea[ET * EDD];  // edge attrs in CSR order (self-loops = mean)
__device__ float g_w[ET * HH];        // un-normalized exp weights (CSR order)

// ---------------- utility ----------------
__global__ void k_zero_i(int* p, int n) {
    int i = blockIdx.x * blockDim.x + threadIdx.x;
    if (i < n) p[i] = 0;
}
__global__ void k_zero_f(float* p, int n) {
    int i = blockIdx.x * blockDim.x + threadIdx.x;
    if (i < n) p[i] = 0.0f;
}

// column sums of edge_attr [E,6]
__global__ void k_meansum(const float* __restrict__ ea) {
    float loc[EDD];
#pragma unroll
    for (int j = 0; j < EDD; j++) loc[j] = 0.0f;
    int i = blockIdx.x * blockDim.x + threadIdx.x;
    int stride = gridDim.x * blockDim.x;
    for (int e = i; e < EE; e += stride) {
#pragma unroll
        for (int j = 0; j < EDD; j++) loc[j] += ea[e * EDD + j];
    }
#pragma unroll
    for (int j = 0; j < EDD; j++) {
        float v = loc[j];
#pragma unroll
        for (int off = 16; off > 0; off >>= 1)
            v += __shfl_down_sync(0xffffffffu, v, off);
        if ((threadIdx.x & 31) == 0) atomicAdd(&g_mesum[j], v);
    }
}

// ---------------- CSR build ----------------
__global__ void k_count(const int* __restrict__ ei) {
    int e = blockIdx.x * blockDim.x + threadIdx.x;
    if (e >= ET) return;
    int dst = (e < EE) ? ei[EE + e] : (e - EE);
    atomicAdd(&g_deg[dst], 1);
}

// single-block exclusive scan of g_deg -> g_start / g_cursor
__global__ __launch_bounds__(1024) void k_scan() {
    __shared__ int warpsum[32];
    __shared__ int carry;
    int tid = threadIdx.x, lane = tid & 31, wid = tid >> 5;
    if (tid == 0) carry = 0;
    __syncthreads();
    for (int base = 0; base < NN; base += 1024) {
        int i = base + tid;
        int v = (i < NN) ? g_deg[i] : 0;
        int x = v;
#pragma unroll
        for (int off = 1; off < 32; off <<= 1) {
            int t = __shfl_up_sync(0xffffffffu, x, off);
            if (lane >= off) x += t;
        }
        if (lane == 31) warpsum[wid] = x;
        __syncthreads();
        if (wid == 0) {
            int s = warpsum[lane];
#pragma unroll
            for (int off = 1; off < 32; off <<= 1) {
                int t = __shfl_up_sync(0xffffffffu, s, off);
                if (lane >= off) s += t;
            }
            warpsum[lane] = s;
        }
        __syncthreads();
        int excl = x - v + (wid > 0 ? warpsum[wid - 1] : 0) + carry;
        if (i < NN) { g_start[i] = excl; g_cursor[i] = excl; }
        __syncthreads();
        if (tid == 1023) carry = excl + v;
        __syncthreads();
    }
    if (threadIdx.x == 0) g_start[NN] = carry;
}

__global__ void k_fill(const int* __restrict__ ei, const float* __restrict__ ea) {
    int e = blockIdx.x * blockDim.x + threadIdx.x;
    if (e >= ET) return;
    int src, dst;
    if (e < EE) { src = ei[e]; dst = ei[EE + e]; }
    else        { src = dst = e - EE; }
    int pos = atomicAdd(&g_cursor[dst], 1);
    g_csr_src[pos] = src;
    if (e < EE) {
#pragma unroll
        for (int j = 0; j < EDD; j++) g_csr_ea[pos * EDD + j] = ea[e * EDD + j];
    } else {
        const float inv = 1.0f / (float)EE;
#pragma unroll
        for (int j = 0; j < EDD; j++) g_csr_ea[pos * EDD + j] = g_mesum[j] * inv;
    }
}

// collapse We (ED,HC) with ae (H,C) -> ve[6,4]
__global__ void k_ve(const float* __restrict__ We, const float* __restrict__ ae) {
    int t = threadIdx.x;
    if (t < EDD * HH) {
        int j = t / HH, h = t % HH;
        float s = 0.0f;
#pragma unroll
        for (int c = 0; c < CC; c++) s += We[j * HC + h * CC + c] * ae[h * CC + c];
        g_ve[j * HH + h] = s;
    }
}

// ---------------- layer-1 GEMM: h = x(N,29) @ W(29,256) ----------------
__global__ __launch_bounds__(256) void k_gemm_l1(const float* __restrict__ x,
                                                 const float* __restrict__ W) {
    __shared__ float fs[32][IND];
    int n0 = blockIdx.x * 32;
    int tid = threadIdx.x;
    for (int i = tid; i < 32 * IND; i += 256) {
        int r = i / IND, k = i % IND;
        int n = n0 + r;
        fs[r][k] = (n < NN) ? x[n * IND + k] : 0.0f;
    }
    float wr[IND];
#pragma unroll
    for (int k = 0; k < IND; k++) wr[k] = __ldg(&W[k * HC + tid]);
    __syncthreads();
#pragma unroll 4
    for (int r = 0; r < 32; r++) {
        int n = n0 + r;
        if (n >= NN) break;
        float s = 0.0f;
#pragma unroll
        for (int k = 0; k < IND; k++) s += fs[r][k] * wr[k];
        g_h[n * HC + tid] = s;
    }
}

// ---------------- layer-2 GEMM: g_h(N,256) = A(N,256) @ W(256,256) ----------------
#define GBM 128
#define GBN 128
#define GBK 8
__global__ __launch_bounds__(256) void k_gemm256(const float* __restrict__ A,
                                                 const float* __restrict__ W) {
    __shared__ float As[GBK][GBM + 4];
    __shared__ float Bs[GBK][GBN];
    int row0 = blockIdx.y * GBM;
    int col0 = blockIdx.x * GBN;
    int tid = threadIdx.x;
    int ar = tid >> 1;
    int ak = (tid & 1) * 4;
    int bk = tid >> 5;
    int bc = (tid & 31) * 4;
    int ty = tid >> 4, tx = tid & 15;
    float acc[8][8];
#pragma unroll
    for (int i = 0; i < 8; i++)
#pragma unroll
        for (int j = 0; j < 8; j++) acc[i][j] = 0.0f;

    for (int k0 = 0; k0 < HC; k0 += GBK) {
        float4 av = make_float4(0.f, 0.f, 0.f, 0.f);
        int arow = row0 + ar;
        if (arow < NN) av = *(const float4*)&A[arow * HC + k0 + ak];
        As[ak + 0][ar] = av.x;
        As[ak + 1][ar] = av.y;
        As[ak + 2][ar] = av.z;
        As[ak + 3][ar] = av.w;
        float4 bv = *(const float4*)&W[(k0 + bk) * HC + col0 + bc];
        *(float4*)&Bs[bk][bc] = bv;
        __syncthreads();
#pragma unroll
        for (int k = 0; k < GBK; k++) {
            float4 a0 = *(const float4*)&As[k][ty * 8];
            float4 a1 = *(const float4*)&As[k][ty * 8 + 4];
            float4 b0 = *(const float4*)&Bs[k][tx * 8];
            float4 b1 = *(const float4*)&Bs[k][tx * 8 + 4];
            float a[8] = {a0.x, a0.y, a0.z, a0.w, a1.x, a1.y, a1.z, a1.w};
            float bb[8] = {b0.x, b0.y, b0.z, b0.w, b1.x, b1.y, b1.z, b1.w};
#pragma unroll
            for (int i = 0; i < 8; i++)
#pragma unroll
                for (int j = 0; j < 8; j++) acc[i][j] += a[i] * bb[j];
        }
        __syncthreads();
    }
#pragma unroll
    for (int i = 0; i < 8; i++) {
        int row = row0 + ty * 8 + i;
        if (row < NN) {
            *(float4*)&g_h[row * HC + col0 + tx * 8] =
                make_float4(acc[i][0], acc[i][1], acc[i][2], acc[i][3]);
            *(float4*)&g_h[row * HC + col0 + tx * 8 + 4] =
                make_float4(acc[i][4], acc[i][5], acc[i][6], acc[i][7]);
        }
    }
}

// ---------------- per-node attention dots ----------------
__global__ __launch_bounds__(256) void k_att(const float* __restrict__ a_s,
                                             const float* __restrict__ a_d) {
    int w = (blockIdx.x * blockDim.x + threadIdx.x) >> 5;
    int lane = threadIdx.x & 31;
    if (w >= NN) return;
    const float* hr = &g_h[w * HC];
    float ps[4] = {0, 0, 0, 0}, pd[4] = {0, 0, 0, 0};
#pragma unroll
    for (int it = 0; it < 8; it++) {
        int j = lane + 32 * it;
        float hv = hr[j];
        ps[it >> 1] += hv * __ldg(&a_s[j]);
        pd[it >> 1] += hv * __ldg(&a_d[j]);
    }
#pragma unroll
    for (int h = 0; h < HH; h++) {
        float v = ps[h], u = pd[h];
#pragma unroll
        for (int off = 16; off > 0; off >>= 1) {
            v += __shfl_down_sync(0xffffffffu, v, off);
            u += __shfl_down_sync(0xffffffffu, u, off);
        }
        if (lane == 0) {
            g_als[w * HH + h] = v;
            g_ald[w * HH + h] = u;
        }
    }
}

// ---------------- fused softmax + aggregate + bias + relu (warp per dst node) ----
__device__ __forceinline__ void edge_alpha(int p, const float ald[4], float a[4]) {
    int src = g_csr_src[p];
    float4 als = *(const float4*)&g_als[src * HH];
    float sa[4] = {als.x, als.y, als.z, als.w};
    float er[EDD];
#pragma unroll
    for (int j = 0; j < EDD; j++) er[j] = g_csr_ea[p * EDD + j];
#pragma unroll
    for (int h = 0; h < HH; h++) {
        float ale = 0.0f;
#pragma unroll
        for (int j = 0; j < EDD; j++) ale += er[j] * __ldg(&g_ve[j * HH + h]);
        float v = sa[h] + ald[h] + ale;
        a[h] = (v > 0.0f) ? v : 0.2f * v;
    }
}

__global__ __launch_bounds__(256) void k_nodeagg(const float* __restrict__ b) {
    int w = (blockIdx.x * blockDim.x + threadIdx.x) >> 5;
    if (w >= NN) return;
    int lane = threadIdx.x & 31;
    int s0 = g_start[w], s1 = g_start[w + 1];
    float4 aldv = *(const float4*)&g_ald[w * HH];
    float ald[4] = {aldv.x, aldv.y, aldv.z, aldv.w};

    // pass 1: per-head max
    float mx[4] = {-1e30f, -1e30f, -1e30f, -1e30f};
    for (int p = s0 + lane; p < s1; p += 32) {
        float a[4];
        edge_alpha(p, ald, a);
#pragma unroll
        for (int h = 0; h < HH; h++) mx[h] = fmaxf(mx[h], a[h]);
    }
#pragma unroll
    for (int h = 0; h < HH; h++)
#pragma unroll
        for (int off = 16; off > 0; off >>= 1)
            mx[h] = fmaxf(mx[h], __shfl_xor_sync(0xffffffffu, mx[h], off));

    // pass 2: exp + denom, store ex to g_w
    float den[4] = {0, 0, 0, 0};
    for (int p = s0 + lane; p < s1; p += 32) {
        float a[4];
        edge_alpha(p, ald, a);
        float ex[4];
#pragma unroll
        for (int h = 0; h < HH; h++) {
            ex[h] = __expf(a[h] - mx[h]);
            den[h] += ex[h];
        }
        *(float4*)&g_w[p * HH] = make_float4(ex[0], ex[1], ex[2], ex[3]);
    }
#pragma unroll
    for (int h = 0; h < HH; h++)
#pragma unroll
        for (int off = 16; off > 0; off >>= 1)
            den[h] += __shfl_xor_sync(0xffffffffu, den[h], off);
    float inv[4];
#pragma unroll
    for (int h = 0; h < HH; h++) inv[h] = 1.0f / (den[h] + 1e-16f);
    __syncwarp();

    // pass 3: weighted gather of h[src], lane owns 8 contiguous cols
    int head = lane >> 3;
    float myinv = inv[head];
    int colbase = lane * 8;
    float acc[8] = {0, 0, 0, 0, 0, 0, 0, 0};
    for (int p = s0; p < s1; p++) {
        int src = g_csr_src[p];
        float wg = g_w[p * HH + head] * myinv;
        const float4* hp = (const float4*)&g_h[src * HC + colbase];
        float4 v0 = hp[0], v1 = hp[1];
        acc[0] += v0.x * wg; acc[1] += v0.y * wg;
        acc[2] += v0.z * wg; acc[3] += v0.w * wg;
        acc[4] += v1.x * wg; acc[5] += v1.y * wg;
        acc[6] += v1.z * wg; acc[7] += v1.w * wg;
    }
    float4 bb0 = __ldg((const float4*)&b[colbase]);
    float4 bb1 = __ldg((const float4*)&b[colbase + 4]);
    float4 o0 = make_float4(fmaxf(acc[0] + bb0.x, 0.f), fmaxf(acc[1] + bb0.y, 0.f),
                            fmaxf(acc[2] + bb0.z, 0.f), fmaxf(acc[3] + bb0.w, 0.f));
    float4 o1 = make_float4(fmaxf(acc[4] + bb1.x, 0.f), fmaxf(acc[5] + bb1.y, 0.f),
                            fmaxf(acc[6] + bb1.z, 0.f), fmaxf(acc[7] + bb1.w, 0.f));
    *(float4*)&g_feat[w * HC + colbase] = o0;
    *(float4*)&g_feat[w * HC + colbase + 4] = o1;
}

// ---------------- fused mean-pool + readout (warp per graph; batch is sorted) ----
__device__ __forceinline__ int lowerb(const int* __restrict__ b, int val) {
    int lo = 0, hi = NN;
    while (lo < hi) {
        int mid = (lo + hi) >> 1;
        if (b[mid] < val) lo = mid + 1; else hi = mid;
    }
    return lo;
}

__global__ __launch_bounds__(256) void k_graph(const int* __restrict__ bat,
                                               const float* __restrict__ Wl,
                                               const float* __restrict__ bl,
                                               float* __restrict__ out) {
    int g = (blockIdx.x * blockDim.x + threadIdx.x) >> 5;
    if (g >= GG) return;
    int lane = threadIdx.x & 31;
    int lo = 0, hi = 0;
    if (lane == 0) {
        lo = lowerb(bat, g);
        hi = lowerb(bat, g + 1);
    }
    lo = __shfl_sync(0xffffffffu, lo, 0);
    hi = __shfl_sync(0xffffffffu, hi, 0);
    float acc[8] = {0, 0, 0, 0, 0, 0, 0, 0};
    int colbase = lane * 8;
    for (int i = lo; i < hi; i++) {
        const float4* fp = (const float4*)&g_feat[i * HC + colbase];
        float4 v0 = fp[0], v1 = fp[1];
        acc[0] += v0.x; acc[1] += v0.y; acc[2] += v0.z; acc[3] += v0.w;
        acc[4] += v1.x; acc[5] += v1.y; acc[6] += v1.z; acc[7] += v1.w;
    }
    float inv = 1.0f / fmaxf((float)(hi - lo), 1.0f);
#pragma unroll
    for (int t = 0; t < NTASK; t++) {
        float p = 0.0f;
#pragma unroll
        for (int k = 0; k < 8; k++)
            p += acc[k] * __ldg(&Wl[(colbase + k) * NTASK + t]);
#pragma unroll
        for (int off = 16; off > 0; off >>= 1)
            p += __shfl_xor_sync(0xffffffffu, p, off);
        if (lane == 0) out[g * NTASK + t] = p * inv + bl[t];
    }
}

// ---------------- host orchestration ----------------
static inline int cdiv(int a, int b) { return (a + b - 1) / b; }

extern "C" void kernel_launch(void* const* d_in, const int* in_sizes, int n_in,
                              void* d_out, int out_size) {
    const float* x   = (const float*)d_in[0];
    const int*   ei  = (const int*)d_in[1];
    const float* ea  = (const float*)d_in[2];
    const int*   bat = (const int*)d_in[3];
    const float* W1  = (const float*)d_in[4];
    const float* as1 = (const float*)d_in[5];
    const float* ad1 = (const float*)d_in[6];
    const float* We1 = (const float*)d_in[7];
    const float* ae1 = (const float*)d_in[8];
    const float* b1  = (const float*)d_in[9];
    const float* W2  = (const float*)d_in[10];
    const float* as2 = (const float*)d_in[11];
    const float* ad2 = (const float*)d_in[12];
    const float* We2 = (const float*)d_in[13];
    const float* ae2 = (const float*)d_in[14];
    const float* b2  = (const float*)d_in[15];
    const float* Wl  = (const float*)d_in[16];
    const float* bl  = (const float*)d_in[17];
    float* out = (float*)d_out;

    float* p_mesum; cudaGetSymbolAddress((void**)&p_mesum, g_mesum);
    int*   p_deg;   cudaGetSymbolAddress((void**)&p_deg, g_deg);
    float* p_feat;  cudaGetSymbolAddress((void**)&p_feat, g_feat);

    // ---- CSR build (shared across layers) ----
    k_zero_f<<<1, 256>>>(p_mesum, EDD);
    k_zero_i<<<cdiv(NN, 256), 256>>>(p_deg, NN);
    k_meansum<<<512, 256>>>(ea);
    k_count<<<cdiv(ET, 256), 256>>>(ei);
    k_scan<<<1, 1024>>>();
    k_fill<<<cdiv(ET, 256), 256>>>(ei, ea);

    // ---- layer 1 ----
    k_ve<<<1, 32>>>(We1, ae1);
    k_gemm_l1<<<cdiv(NN, 32), 256>>>(x, W1);
    k_att<<<cdiv(NN * 32, 256), 256>>>(as1, ad1);
    k_nodeagg<<<cdiv(NN * 32, 256), 256>>>(b1);

    // ---- layer 2 ----
    k_ve<<<1, 32>>>(We2, ae2);
    {
        dim3 grid(HC / GBN, cdiv(NN, GBM));
        k_gemm256<<<grid, 256>>>(p_feat, W2);
    }
    k_att<<<cdiv(NN * 32, 256), 256>>>(as2, ad2);
    k_nodeagg<<<cdiv(NN * 32, 256), 256>>>(b2);

    // ---- readout ----
    k_graph<<<cdiv(GG * 32, 256), 256>>>(bat, Wl, bl, out);
}